// round 6
// baseline (speedup 1.0000x reference)
#include <cuda_runtime.h>
#include <cstdint>

// Problem: B=32, N=8192, DIM=256, M=1228
//   in0: x            [B, N, DIM] float32
//   in1: mask_indices [B, M]      int32
//   in2: emb_mask     [1, DIM]    float32
// out: masked_x [B*N*DIM] floats (+ mask_indices as floats if room).

#define DIM      256
#define ROWS_PB  256    // rows per block (divides N); 256 flags = 8 uint32
#define THREADS  256
#define UNROLL   2      // staging regs: 2 x float4 = 8 regs

__global__ void __launch_bounds__(THREADS, 8)   // force <=32 regs -> 8 blocks/SM
fused_mask_kernel(const float* __restrict__ x,
                  const int*   __restrict__ mask_indices,
                  const float* __restrict__ emb_mask,
                  float*       __restrict__ out,
                  float*       __restrict__ out_idx,   // may be null
                  int M, int N, int blocks_per_batch)
{
    __shared__ uint32_t fl[ROWS_PB / 32];   // bitmask of masked rows (8 words)

    const int tid = threadIdx.x;
    const int b   = blockIdx.x / blocks_per_batch;
    const int blk = blockIdx.x % blocks_per_batch;
    const int r0  = blk * ROWS_PB;

    if (tid < ROWS_PB / 32) fl[tid] = 0;
    __syncthreads();

    // scan this batch's indices; set bits for rows in our range
    const int* idx_row = mask_indices + (size_t)b * M;
    for (int i = tid; i < M; i += THREADS) {
        int idx   = idx_row[i];
        int local = idx - r0;
        if ((unsigned)local < (unsigned)ROWS_PB)
            atomicOr(&fl[local >> 5], 1u << (local & 31));
        if (blk == 0 && out_idx != nullptr)
            out_idx[(size_t)b * M + i] = (float)idx;  // idx < 8192: exact in fp32
    }
    __syncthreads();

    const int sub  = tid >> 6;        // 0..3: row lane within a group of 4 rows
    const int col4 = tid & 63;        // float4 lane within row

    const float4 emb = reinterpret_cast<const float4*>(emb_mask)[col4];

    const size_t base = ((size_t)b * N + r0) * (DIM / 4);
    const float4* __restrict__ src = reinterpret_cast<const float4*>(x) + base;
    float4*       __restrict__ dst = reinterpret_cast<float4*>(out)     + base;

    // 64 row-iterations per thread; groups of UNROLL (flags read via smem
    // broadcast each iteration — latency hidden by high occupancy)
    #pragma unroll
    for (int it = 0; it < ROWS_PB / 4; it += UNROLL) {
        float4 v[UNROLL];
        #pragma unroll
        for (int u = 0; u < UNROLL; ++u) {
            const int row = (it + u) * 4 + sub;
            const size_t off = (size_t)row * (DIM / 4) + col4;
            const bool masked = (fl[row >> 5] >> (row & 31)) & 1u;
            v[u] = masked ? emb : __ldcs(&src[off]);
        }
        #pragma unroll
        for (int u = 0; u < UNROLL; ++u) {
            const int row = (it + u) * 4 + sub;
            const size_t off = (size_t)row * (DIM / 4) + col4;
            __stcs(&dst[off], v[u]);
        }
    }
}

extern "C" void kernel_launch(void* const* d_in, const int* in_sizes, int n_in,
                              void* d_out, int out_size)
{
    const float* x            = (const float*)d_in[0];
    const int*   mask_indices = (const int*)d_in[1];
    const float* emb_mask     = (const float*)d_in[2];
    float*       out          = (float*)d_out;

    const int x_elems   = in_sizes[0];          // B*N*DIM
    const int idx_elems = in_sizes[1];          // B*M
    const int BN        = x_elems / DIM;        // B*N
    const int N         = 8192;
    const int B         = BN / N;
    const int M         = idx_elems / B;

    float* out_idx = (out_size >= x_elems + idx_elems)
                   ? (out + x_elems) : nullptr;

    const int blocks_per_batch = N / ROWS_PB;   // 32
    fused_mask_kernel<<<B * blocks_per_batch, THREADS>>>(
        x, mask_indices, emb_mask, out, out_idx, M, N, blocks_per_batch);
}

// round 7
// speedup vs baseline: 1.0471x; 1.0471x over previous
#include <cuda_runtime.h>
#include <cstdint>

// Problem: B=32, N=8192, DIM=256, M=1228
//   in0: x            [B, N, DIM] float32
//   in1: mask_indices [B, M]      int32
//   in2: emb_mask     [1, DIM]    float32
// out: masked_x [B*N*DIM] floats (+ mask_indices as floats if room).

#define DIM      256
#define ROWS_PB  256    // rows per block (divides N); 256 flags = 8 uint32
#define THREADS  256
#define UNROLL   4      // staging regs: 4 x float4 = 16 regs

__global__ void __launch_bounds__(THREADS, 5)   // cap ~51 regs -> 5 blocks/SM
fused_mask_kernel(const float* __restrict__ x,
                  const int*   __restrict__ mask_indices,
                  const float* __restrict__ emb_mask,
                  float*       __restrict__ out,
                  float*       __restrict__ out_idx,   // may be null
                  int M, int N, int blocks_per_batch)
{
    __shared__ uint32_t fl[ROWS_PB / 32];   // bitmask of masked rows (8 words)

    const int tid = threadIdx.x;
    const int b   = blockIdx.x / blocks_per_batch;
    const int blk = blockIdx.x % blocks_per_batch;
    const int r0  = blk * ROWS_PB;

    if (tid < ROWS_PB / 32) fl[tid] = 0;
    __syncthreads();

    // scan this batch's indices; set bits for rows in our range
    const int* idx_row = mask_indices + (size_t)b * M;
    for (int i = tid; i < M; i += THREADS) {
        int idx   = idx_row[i];
        int local = idx - r0;
        if ((unsigned)local < (unsigned)ROWS_PB)
            atomicOr(&fl[local >> 5], 1u << (local & 31));
        if (blk == 0 && out_idx != nullptr)
            out_idx[(size_t)b * M + i] = (float)idx;  // idx < 8192: exact in fp32
    }
    __syncthreads();

    // bitmask into registers (broadcast LDS once, conflict-free)
    uint32_t fw[ROWS_PB / 32];
    #pragma unroll
    for (int w = 0; w < ROWS_PB / 32; ++w) fw[w] = fl[w];

    const int sub  = tid >> 6;        // 0..3: row lane within a group of 4 rows
    const int col4 = tid & 63;        // float4 lane within row

    const float4 emb = reinterpret_cast<const float4*>(emb_mask)[col4];

    const size_t base = ((size_t)b * N + r0) * (DIM / 4);
    const float4* __restrict__ src = reinterpret_cast<const float4*>(x) + base;
    float4*       __restrict__ dst = reinterpret_cast<float4*>(out)     + base;

    // 64 row-iterations per thread; rolled outer loop (keeps regs low),
    // fully-unrolled UNROLL-wide load batch for MLP=4.
    #pragma unroll 1
    for (int it = 0; it < ROWS_PB / 4; it += UNROLL) {
        float4 v[UNROLL];
        #pragma unroll
        for (int u = 0; u < UNROLL; ++u) {
            const int row = (it + u) * 4 + sub;
            const size_t off = (size_t)row * (DIM / 4) + col4;
            const bool masked = (fw[row >> 5] >> (row & 31)) & 1u;
            v[u] = masked ? emb : __ldcs(&src[off]);
        }
        #pragma unroll
        for (int u = 0; u < UNROLL; ++u) {
            const int row = (it + u) * 4 + sub;
            const size_t off = (size_t)row * (DIM / 4) + col4;
            __stcs(&dst[off], v[u]);
        }
    }
}

extern "C" void kernel_launch(void* const* d_in, const int* in_sizes, int n_in,
                              void* d_out, int out_size)
{
    const float* x            = (const float*)d_in[0];
    const int*   mask_indices = (const int*)d_in[1];
    const float* emb_mask     = (const float*)d_in[2];
    float*       out          = (float*)d_out;

    const int x_elems   = in_sizes[0];          // B*N*DIM
    const int idx_elems = in_sizes[1];          // B*M
    const int BN        = x_elems / DIM;        // B*N
    const int N         = 8192;
    const int B         = BN / N;
    const int M         = idx_elems / B;

    float* out_idx = (out_size >= x_elems + idx_elems)
                   ? (out + x_elems) : nullptr;

    const int blocks_per_batch = N / ROWS_PB;   // 32
    fused_mask_kernel<<<B * blocks_per_batch, THREADS>>>(
        x, mask_indices, emb_mask, out, out_idx, M, N, blocks_per_batch);
}